// round 1
// baseline (speedup 1.0000x reference)
#include <cuda_runtime.h>
#include <cstdint>

#define NE   8
#define DIM  2048
#define FFN  5632
#define NT   4096

#define BM   128
#define BN   64
#define BK   32
#define LDS_ 36
#define ASTAGE (BM*LDS_)
#define BSTAGE (BN*LDS_)

// ---------------- device scratch (static; no allocation) ----------------
__device__ int   g_counts[NE];
__device__ int   g_token_of[NE*NT];
__device__ int   g_slot_of[NT*NE];
__device__ float g_h[(size_t)NE*NT*FFN];   // ~738 MB
__device__ float g_y[(size_t)NE*NT*DIM];   // ~268 MB

// ---------------- helpers ----------------
__device__ __forceinline__ unsigned sptr(const void* p) {
    return (unsigned)__cvta_generic_to_shared(p);
}
__device__ __forceinline__ void cp16(unsigned dst, const void* src) {
    asm volatile("cp.async.cg.shared.global [%0], [%1], 16;\n" :: "r"(dst), "l"(src));
}
__device__ __forceinline__ void cp_commit() { asm volatile("cp.async.commit_group;\n" ::: "memory"); }
__device__ __forceinline__ void cp_wait1()  { asm volatile("cp.async.wait_group 1;\n" ::: "memory"); }
__device__ __forceinline__ void cp_wait0()  { asm volatile("cp.async.wait_group 0;\n" ::: "memory"); }

__device__ __forceinline__ uint32_t to_tf32(float f) {
    uint32_t r; asm("cvt.rna.tf32.f32 %0, %1;" : "=r"(r) : "f"(f)); return r;
}
__device__ __forceinline__ void mma_tf32(float c[4], const uint32_t a[4], const uint32_t b[2]) {
    asm volatile(
        "mma.sync.aligned.m16n8k8.row.col.f32.tf32.tf32.f32 "
        "{%0,%1,%2,%3}, {%4,%5,%6,%7}, {%8,%9}, {%0,%1,%2,%3};\n"
        : "+f"(c[0]), "+f"(c[1]), "+f"(c[2]), "+f"(c[3])
        : "r"(a[0]), "r"(a[1]), "r"(a[2]), "r"(a[3]), "r"(b[0]), "r"(b[1]));
}
__device__ __forceinline__ float silu_mul(float u, float v) {
    return v * (u / (1.0f + __expf(-u)));
}

// ---------------- routing ----------------
__global__ void zero_counts_k() {
    if (threadIdx.x < NE) g_counts[threadIdx.x] = 0;
}

__global__ void route_k(const int* __restrict__ map) {
    int t = blockIdx.x * blockDim.x + threadIdx.x;
    if (t >= NT) return;
    #pragma unroll
    for (int e = 0; e < NE; e++) {
        if (map[t*NE + e]) {
            int s = atomicAdd(&g_counts[e], 1);
            g_token_of[e*NT + s] = t;
            g_slot_of[t*NE + e]  = s;
        }
    }
}

// ---------------- GEMM1+GEMM3 fused + SwiGLU ----------------
// grid = (Mtiles=32 [fastest -> L2 B-sharing], Ntiles=FFN/64, experts=8)
__global__ void __launch_bounds__(256, 2)
gemm1_k(const float* __restrict__ x,
        const float* __restrict__ w1, const float* __restrict__ w3) {
    const int e   = blockIdx.z;
    const int cnt = g_counts[e];
    const int m0  = blockIdx.x * BM;
    if (m0 >= cnt) return;
    const int n0  = blockIdx.y * BN;

    extern __shared__ float sm[];
    float* As  = sm;                    // 2 * 128*36
    float* B1s = sm + 2*ASTAGE;         // 2 * 64*36
    float* B3s = B1s + 2*BSTAGE;        // 2 * 64*36

    const int tid = threadIdx.x;
    const int c4  = (tid & 7) * 4;      // float offset within 32-col slice
    const int r0  = tid >> 3;           // 0..31

    // A: gathered token rows; 4 rows per thread (clamp out-of-range slots to slot 0)
    const float* a_src[4];
    unsigned a_off[4];
    #pragma unroll
    for (int t = 0; t < 4; t++) {
        int r = r0 + t*32;
        int slot = m0 + r;
        int tok = (slot < cnt) ? g_token_of[e*NT + slot] : g_token_of[e*NT];
        a_src[t] = x + (size_t)tok*DIM + c4;
        a_off[t] = r*LDS_ + c4;
    }
    const float* b1p0 = w1 + ((size_t)e*FFN + n0 + r0)*DIM + c4;
    const float* b1p1 = b1p0 + (size_t)32*DIM;
    const float* b3p0 = w3 + ((size_t)e*FFN + n0 + r0)*DIM + c4;
    const float* b3p1 = b3p0 + (size_t)32*DIM;
    const unsigned bo0 = r0*LDS_ + c4, bo1 = (r0+32)*LDS_ + c4;

    auto prefetch = [&](int stage, int k) {
        float* Ast = As  + stage*ASTAGE;
        float* B1t = B1s + stage*BSTAGE;
        float* B3t = B3s + stage*BSTAGE;
        #pragma unroll
        for (int t = 0; t < 4; t++) cp16(sptr(Ast + a_off[t]), a_src[t] + k);
        cp16(sptr(B1t + bo0), b1p0 + k);
        cp16(sptr(B1t + bo1), b1p1 + k);
        cp16(sptr(B3t + bo0), b3p0 + k);
        cp16(sptr(B3t + bo1), b3p1 + k);
        cp_commit();
    };

    const int lane = tid & 31, wid = tid >> 5;
    const int wm = (wid & 3) * 32, wn = (wid >> 2) * 32;
    const int g = lane >> 2, tg = lane & 3;

    float acc1[2][4][4] = {}, acc3[2][4][4] = {};

    const int KT = DIM / BK;   // 64
    prefetch(0, 0);
    for (int kt = 0; kt < KT; kt++) {
        if (kt + 1 < KT) { prefetch((kt+1)&1, (kt+1)*BK); cp_wait1(); }
        else             { cp_wait0(); }
        __syncthreads();
        const float* Ast = As  + (kt&1)*ASTAGE;
        const float* B1t = B1s + (kt&1)*BSTAGE;
        const float* B3t = B3s + (kt&1)*BSTAGE;
        #pragma unroll
        for (int kk = 0; kk < 4; kk++) {
            const int kc = kk*8 + tg;
            uint32_t a[2][4];
            #pragma unroll
            for (int mi = 0; mi < 2; mi++) {
                int row = wm + mi*16 + g;
                a[mi][0] = to_tf32(Ast[row     *LDS_ + kc]);
                a[mi][1] = to_tf32(Ast[(row+8) *LDS_ + kc]);
                a[mi][2] = to_tf32(Ast[row     *LDS_ + kc + 4]);
                a[mi][3] = to_tf32(Ast[(row+8) *LDS_ + kc + 4]);
            }
            #pragma unroll
            for (int ni = 0; ni < 4; ni++) {
                int brow = wn + ni*8 + g;
                uint32_t b1[2], b3[2];
                b1[0] = to_tf32(B1t[brow*LDS_ + kc]);
                b1[1] = to_tf32(B1t[brow*LDS_ + kc + 4]);
                b3[0] = to_tf32(B3t[brow*LDS_ + kc]);
                b3[1] = to_tf32(B3t[brow*LDS_ + kc + 4]);
                #pragma unroll
                for (int mi = 0; mi < 2; mi++) {
                    mma_tf32(acc1[mi][ni], a[mi], b1);
                    mma_tf32(acc3[mi][ni], a[mi], b3);
                }
            }
        }
        __syncthreads();
    }

    // epilogue: h = silu(u) * v  (rows beyond cnt hold garbage, never read)
    #pragma unroll
    for (int mi = 0; mi < 2; mi++) {
        #pragma unroll
        for (int ni = 0; ni < 4; ni++) {
            int row = wm + mi*16 + g;
            int col = wn + ni*8 + tg*2;
            size_t base = ((size_t)(e*NT + m0 + row))*FFN + n0 + col;
            float u0 = acc1[mi][ni][0], u1 = acc1[mi][ni][1];
            float v0 = acc3[mi][ni][0], v1 = acc3[mi][ni][1];
            *(float2*)&g_h[base] = make_float2(silu_mul(u0, v0), silu_mul(u1, v1));
            float u2 = acc1[mi][ni][2], u3 = acc1[mi][ni][3];
            float v2 = acc3[mi][ni][2], v3 = acc3[mi][ni][3];
            *(float2*)&g_h[base + (size_t)8*FFN] = make_float2(silu_mul(u2, v2), silu_mul(u3, v3));
        }
    }
}

// ---------------- GEMM2: y = h @ w2[e]^T ----------------
__global__ void __launch_bounds__(256, 2)
gemm2_k(const float* __restrict__ w2) {
    const int e   = blockIdx.z;
    const int cnt = g_counts[e];
    const int m0  = blockIdx.x * BM;
    if (m0 >= cnt) return;
    const int n0  = blockIdx.y * BN;

    extern __shared__ float sm[];
    float* As = sm;                 // 2 * 128*36
    float* Bs = sm + 2*ASTAGE;      // 2 * 64*36

    const int tid = threadIdx.x;
    const int c4  = (tid & 7) * 4;
    const int r0  = tid >> 3;

    const float* a_src[4];
    unsigned a_off[4];
    #pragma unroll
    for (int t = 0; t < 4; t++) {
        int r = r0 + t*32;
        a_src[t] = g_h + ((size_t)(e*NT + m0 + r))*FFN + c4;  // always in-bounds
        a_off[t] = r*LDS_ + c4;
    }
    const float* bp0 = w2 + ((size_t)e*DIM + n0 + r0)*FFN + c4;
    const float* bp1 = bp0 + (size_t)32*FFN;
    const unsigned bo0 = r0*LDS_ + c4, bo1 = (r0+32)*LDS_ + c4;

    auto prefetch = [&](int stage, int k) {
        float* Ast = As + stage*ASTAGE;
        float* Bt  = Bs + stage*BSTAGE;
        #pragma unroll
        for (int t = 0; t < 4; t++) cp16(sptr(Ast + a_off[t]), a_src[t] + k);
        cp16(sptr(Bt + bo0), bp0 + k);
        cp16(sptr(Bt + bo1), bp1 + k);
        cp_commit();
    };

    const int lane = tid & 31, wid = tid >> 5;
    const int wm = (wid & 3) * 32, wn = (wid >> 2) * 32;
    const int g = lane >> 2, tg = lane & 3;

    float acc[2][4][4] = {};

    const int KT = FFN / BK;   // 176
    prefetch(0, 0);
    for (int kt = 0; kt < KT; kt++) {
        if (kt + 1 < KT) { prefetch((kt+1)&1, (kt+1)*BK); cp_wait1(); }
        else             { cp_wait0(); }
        __syncthreads();
        const float* Ast = As + (kt&1)*ASTAGE;
        const float* Bt  = Bs + (kt&1)*BSTAGE;
        #pragma unroll
        for (int kk = 0; kk < 4; kk++) {
            const int kc = kk*8 + tg;
            uint32_t a[2][4];
            #pragma unroll
            for (int mi = 0; mi < 2; mi++) {
                int row = wm + mi*16 + g;
                a[mi][0] = to_tf32(Ast[row     *LDS_ + kc]);
                a[mi][1] = to_tf32(Ast[(row+8) *LDS_ + kc]);
                a[mi][2] = to_tf32(Ast[row     *LDS_ + kc + 4]);
                a[mi][3] = to_tf32(Ast[(row+8) *LDS_ + kc + 4]);
            }
            #pragma unroll
            for (int ni = 0; ni < 4; ni++) {
                int brow = wn + ni*8 + g;
                uint32_t b[2];
                b[0] = to_tf32(Bt[brow*LDS_ + kc]);
                b[1] = to_tf32(Bt[brow*LDS_ + kc + 4]);
                #pragma unroll
                for (int mi = 0; mi < 2; mi++) mma_tf32(acc[mi][ni], a[mi], b);
            }
        }
        __syncthreads();
    }

    #pragma unroll
    for (int mi = 0; mi < 2; mi++) {
        #pragma unroll
        for (int ni = 0; ni < 4; ni++) {
            int row = wm + mi*16 + g;
            int col = wn + ni*8 + tg*2;
            size_t base = ((size_t)(e*NT + m0 + row))*DIM + n0 + col;
            *(float2*)&g_y[base]                 = make_float2(acc[mi][ni][0], acc[mi][ni][1]);
            *(float2*)&g_y[base + (size_t)8*DIM] = make_float2(acc[mi][ni][2], acc[mi][ni][3]);
        }
    }
}

// ---------------- final gather: out[t] = sum_e p[t,e] * y[e, slot(t,e)] ----------------
__global__ void gather_k(const int* __restrict__ map, const float* __restrict__ probs,
                         float* __restrict__ out) {
    const int t = blockIdx.x;
    const int tid = threadIdx.x;
    float4 acc0 = make_float4(0.f, 0.f, 0.f, 0.f);
    float4 acc1 = make_float4(0.f, 0.f, 0.f, 0.f);
    #pragma unroll
    for (int e = 0; e < NE; e++) {
        if (map[t*NE + e]) {
            float p = probs[t*NE + e];
            int slot = g_slot_of[t*NE + e];
            const float4* yr = (const float4*)(g_y + ((size_t)(e*NT + slot))*DIM);
            float4 y0 = yr[tid], y1 = yr[tid + 256];
            acc0.x += p*y0.x; acc0.y += p*y0.y; acc0.z += p*y0.z; acc0.w += p*y0.w;
            acc1.x += p*y1.x; acc1.y += p*y1.y; acc1.z += p*y1.z; acc1.w += p*y1.w;
        }
    }
    float4* o = (float4*)(out + (size_t)t*DIM);
    o[tid]       = acc0;
    o[tid + 256] = acc1;
}

// ---------------- launch ----------------
extern "C" void kernel_launch(void* const* d_in, const int* in_sizes, int n_in,
                              void* d_out, int out_size) {
    const float* x     = (const float*)d_in[0];
    const int*   map   = (const int*)  d_in[1];
    const float* probs = (const float*)d_in[2];
    const float* w1    = (const float*)d_in[3];
    const float* w2    = (const float*)d_in[4];
    const float* w3    = (const float*)d_in[5];
    float*       out   = (float*)d_out;

    const int smem1 = 2*(ASTAGE + 2*BSTAGE)*4;   // 73728 B
    const int smem2 = 2*(ASTAGE +   BSTAGE)*4;   // 55296 B
    cudaFuncSetAttribute(gemm1_k, cudaFuncAttributeMaxDynamicSharedMemorySize, smem1);
    cudaFuncSetAttribute(gemm2_k, cudaFuncAttributeMaxDynamicSharedMemorySize, smem2);

    zero_counts_k<<<1, 32>>>();
    route_k<<<(NT + 255)/256, 256>>>(map);
    gemm1_k<<<dim3(NT/BM, FFN/BN, NE), 256, smem1>>>(x, w1, w3);
    gemm2_k<<<dim3(NT/BM, DIM/BN, NE), 256, smem2>>>(w2);
    gather_k<<<NT, 256>>>(map, probs, out);
}

// round 4
// speedup vs baseline: 1.2811x; 1.2811x over previous
#include <cuda_runtime.h>
#include <cuda.h>
#include <cudaTypedefs.h>
#include <cstdint>

#define NE   8
#define DIM  2048
#define FFN  5632
#define NT   4096
#define NROWS 10240             // >= 8192 routed rows + 8*127 pad, 128-aligned

#define BM   128
#define BN   64
#define BK   32                 // floats per k-tile = 128B row = SW128 atom
#define KT1  (DIM/BK)           // 64
#define KT2  (FFN/BK)           // 176
#define ST1  3
#define ST2  3

#define A_BYTES (BM*128)        // 16384
#define B_BYTES (BN*128)        // 8192

// ctrl block (1KB), then stages
#define FULL_OFF(s)  (0  + 8*(s))
#define EMPTY_OFF(s) (64 + 8*(s))
#define SM1_STAGE (A_BYTES + 2*B_BYTES)          // 32768
#define SM1_A(s)  (1024 + (s)*SM1_STAGE)
#define SM1_B1(s) (SM1_A(s) + A_BYTES)
#define SM1_B3(s) (SM1_B1(s) + B_BYTES)
#define SM1_TOTAL (1024 + ST1*SM1_STAGE)         // 99328
#define SM2_STAGE (A_BYTES + B_BYTES)            // 24576
#define SM2_A(s)  (1024 + (s)*SM2_STAGE)
#define SM2_B(s)  (SM2_A(s) + A_BYTES)
#define SM2_TOTAL (1024 + ST2*SM2_STAGE)         // 74752

// ---------------- device scratch (static; total ~1.50 GB < 2 GB link limit) ----------------
__device__ int   g_counts[NE];
__device__ int   g_base[NE];
__device__ int   g_slot_of[NT*NE];
__device__ float g_xp[(size_t)NROWS*DIM];        // 80 MB  permuted + RNE-rounded x
__device__ float g_w1[(size_t)NE*FFN*DIM];       // 369 MB RNE-rounded weights
__device__ float g_w2[(size_t)NE*DIM*FFN];       // 369 MB
__device__ float g_w3[(size_t)NE*FFN*DIM];       // 369 MB
__device__ float g_h[(size_t)NROWS*FFN];         // 230 MB
__device__ float g_y[(size_t)NROWS*DIM];         // 80 MB

// ---------------- helpers ----------------
__device__ __forceinline__ uint32_t smem_u32(const void* p) {
    uint32_t a;
    asm("{ .reg .u64 t; cvta.to.shared.u64 t, %1; cvt.u32.u64 %0, t; }" : "=r"(a) : "l"(p));
    return a;
}
__device__ __forceinline__ bool elect_one() {
    uint32_t pred;
    asm volatile("{\n\t.reg .pred p;\n\telect.sync _|p, 0xFFFFFFFF;\n\tselp.b32 %0, 1, 0, p;\n\t}"
                 : "=r"(pred));
    return pred != 0;
}
#define MBAR_INIT(addr, cnt) \
    asm volatile("mbarrier.init.shared.b64 [%0], %1;" :: "r"((uint32_t)(addr)), "r"((uint32_t)(cnt)) : "memory")
#define MBAR_EXPECT_TX(addr, bytes) \
    asm volatile("mbarrier.arrive.expect_tx.shared.b64 _, [%0], %1;" :: "r"((uint32_t)(addr)), "r"((uint32_t)(bytes)) : "memory")
#define MBAR_ARRIVE(addr) \
    asm volatile("mbarrier.arrive.shared.b64 _, [%0];" :: "r"((uint32_t)(addr)) : "memory")
#define MBAR_WAIT(addr, ph) do { \
    asm volatile("{\n\t.reg .pred P1;\n\t" \
        "WAIT_%=:\n\t" \
        "mbarrier.try_wait.parity.acquire.cta.shared::cta.b64 P1, [%0], %1, 0x989680;\n\t" \
        "@P1 bra.uni DONE_%=;\n\t" \
        "bra.uni WAIT_%=;\n\t" \
        "DONE_%=:\n\t}" \
        :: "r"((uint32_t)(addr)), "r"((uint32_t)(ph)) : "memory"); \
} while (0)

__device__ __forceinline__ void tma2d(uint32_t dst, const CUtensorMap* m, int x, int y, uint32_t bar) {
    asm volatile(
        "cp.async.bulk.tensor.2d.shared::cta.global.tile.mbarrier::complete_tx::bytes "
        "[%0], [%1, {%2, %3}], [%4];"
        :: "r"(dst), "l"(m), "r"(x), "r"(y), "r"(bar) : "memory");
}
__device__ __forceinline__ void mma_tf32(float c[4], const uint32_t a[4], const uint32_t b[2]) {
    asm volatile(
        "mma.sync.aligned.m16n8k8.row.col.f32.tf32.tf32.f32 "
        "{%0,%1,%2,%3}, {%4,%5,%6,%7}, {%8,%9}, {%0,%1,%2,%3};\n"
        : "+f"(c[0]), "+f"(c[1]), "+f"(c[2]), "+f"(c[3])
        : "r"(a[0]), "r"(a[1]), "r"(a[2]), "r"(a[3]), "r"(b[0]), "r"(b[1]));
}
__device__ __forceinline__ uint32_t tf32_bits(float f) {
    uint32_t r; asm("cvt.rna.tf32.f32 %0, %1;" : "=r"(r) : "f"(f)); return r;
}
__device__ __forceinline__ float rnef(float f) { return __uint_as_float(tf32_bits(f)); }
__device__ __forceinline__ uint32_t lds_u32(uint32_t addr) {
    uint32_t v; asm volatile("ld.shared.b32 %0, [%1];" : "=r"(v) : "r"(addr)); return v;
}

// ---------------- routing / prep ----------------
__global__ void zero_counts_k() { if (threadIdx.x < NE) g_counts[threadIdx.x] = 0; }

__global__ void route_k(const int* __restrict__ map) {
    int t = blockIdx.x * blockDim.x + threadIdx.x;
    if (t >= NT) return;
    #pragma unroll
    for (int e = 0; e < NE; e++) {
        if (map[t*NE + e]) {
            int s = atomicAdd(&g_counts[e], 1);
            g_slot_of[t*NE + e] = s;
        }
    }
}

__global__ void base_k() {     // 128-aligned exclusive prefix of counts
    if (threadIdx.x == 0) {
        int acc = 0;
        #pragma unroll
        for (int e = 0; e < NE; e++) {
            g_base[e] = acc;
            acc += (g_counts[e] + 127) & ~127;
        }
    }
}

__global__ void permute_round_k(const float* __restrict__ x, const int* __restrict__ map) {
    const int t = blockIdx.x, tid = threadIdx.x;
    const float4* xr = (const float4*)(x + (size_t)t*DIM);
    float4 a = xr[tid], b = xr[tid + 256];
    a.x = rnef(a.x); a.y = rnef(a.y); a.z = rnef(a.z); a.w = rnef(a.w);
    b.x = rnef(b.x); b.y = rnef(b.y); b.z = rnef(b.z); b.w = rnef(b.w);
    #pragma unroll
    for (int e = 0; e < NE; e++) {
        if (map[t*NE + e]) {
            int row = g_base[e] + g_slot_of[t*NE + e];
            float4* d = (float4*)(g_xp + (size_t)row*DIM);
            d[tid] = a; d[tid + 256] = b;
        }
    }
}

__global__ void round_k(const float4* __restrict__ src, float4* __restrict__ dst, int n4) {
    int i = blockIdx.x * blockDim.x + threadIdx.x;
    if (i >= n4) return;
    float4 v = src[i];
    v.x = rnef(v.x); v.y = rnef(v.y); v.z = rnef(v.z); v.w = rnef(v.w);
    dst[i] = v;
}

// ---------------- GEMM1: u=Xp@W1^T, v=Xp@W3^T, h=silu(u)*v ----------------
// 288 threads: warps 0-7 consume (32x32 warp tiles), warp 8 = TMA producer.
__global__ void __launch_bounds__(288, 2)
gemm1_k(const __grid_constant__ CUtensorMap a_map,
        const __grid_constant__ CUtensorMap b1_map,
        const __grid_constant__ CUtensorMap b3_map)
{
    const int e = blockIdx.z;
    const int cnt = g_counts[e];
    const int m0 = blockIdx.x * BM;
    if (m0 >= cnt) return;
    const int base = g_base[e];
    const int n0 = blockIdx.y * BN;

    extern __shared__ __align__(1024) char smem[];
    const uint32_t sb = smem_u32(smem);
    const int tid = threadIdx.x, wid = tid >> 5, lane = tid & 31;

    if (tid == 0) {
        #pragma unroll
        for (int s = 0; s < ST1; s++) { MBAR_INIT(sb+FULL_OFF(s), 1); MBAR_INIT(sb+EMPTY_OFF(s), 8); }
    }
    __syncthreads();

    if (wid == 8) {                 // ---- TMA producer ----
        int s = 0, ph = 1;
        #pragma unroll 1
        for (int kt = 0; kt < KT1; kt++) {
            MBAR_WAIT(sb+EMPTY_OFF(s), ph);
            if (elect_one()) {
                MBAR_EXPECT_TX(sb+FULL_OFF(s), A_BYTES + 2*B_BYTES);
                tma2d(sb+SM1_A(s),  &a_map,  kt*BK, base + m0,  sb+FULL_OFF(s));
                tma2d(sb+SM1_B1(s), &b1_map, kt*BK, e*FFN + n0, sb+FULL_OFF(s));
                tma2d(sb+SM1_B3(s), &b3_map, kt*BK, e*FFN + n0, sb+FULL_OFF(s));
            }
            if (++s == ST1) { s = 0; ph ^= 1; }
        }
        return;
    }

    // ---- consumer ----
    const int wm = (wid & 3) * 32, wn = (wid >> 2) * 32;
    const int g = lane >> 2, tg = lane & 3;
    const uint32_t mk = (uint32_t)g << 4;               // SW128 swizzle mask (row&7 == g)

    uint32_t aRow[4], bRow[4], cofs[4][2];
    #pragma unroll
    for (int i = 0; i < 4; i++) aRow[i] = (uint32_t)(wm + g + i*8) * 128;
    #pragma unroll
    for (int i = 0; i < 4; i++) bRow[i] = (uint32_t)(wn + i*8 + g) * 128;
    #pragma unroll
    for (int kk = 0; kk < 4; kk++) {
        cofs[kk][0] = ((uint32_t)(kk*8 + tg)     * 4) ^ mk;
        cofs[kk][1] = ((uint32_t)(kk*8 + tg + 4) * 4) ^ mk;
    }

    float acc1[2][4][4] = {}, acc3[2][4][4] = {};
    int s = 0, ph = 0;
    #pragma unroll 1
    for (int kt = 0; kt < KT1; kt++) {
        MBAR_WAIT(sb+FULL_OFF(s), ph);
        const uint32_t At = sb + SM1_A(s), B1t = sb + SM1_B1(s), B3t = sb + SM1_B3(s);
        #pragma unroll
        for (int kk = 0; kk < 4; kk++) {
            uint32_t a[2][4];
            #pragma unroll
            for (int mi = 0; mi < 2; mi++) {
                a[mi][0] = lds_u32(At + aRow[2*mi]   + cofs[kk][0]);
                a[mi][1] = lds_u32(At + aRow[2*mi+1] + cofs[kk][0]);
                a[mi][2] = lds_u32(At + aRow[2*mi]   + cofs[kk][1]);
                a[mi][3] = lds_u32(At + aRow[2*mi+1] + cofs[kk][1]);
            }
            #pragma unroll
            for (int ni = 0; ni < 4; ni++) {
                uint32_t b1[2], b3[2];
                b1[0] = lds_u32(B1t + bRow[ni] + cofs[kk][0]);
                b1[1] = lds_u32(B1t + bRow[ni] + cofs[kk][1]);
                b3[0] = lds_u32(B3t + bRow[ni] + cofs[kk][0]);
                b3[1] = lds_u32(B3t + bRow[ni] + cofs[kk][1]);
                #pragma unroll
                for (int mi = 0; mi < 2; mi++) {
                    mma_tf32(acc1[mi][ni], a[mi], b1);
                    mma_tf32(acc3[mi][ni], a[mi], b3);
                }
            }
        }
        __syncwarp();
        if (lane == 0) MBAR_ARRIVE(sb+EMPTY_OFF(s));
        if (++s == ST1) { s = 0; ph ^= 1; }
    }

    // epilogue: h = silu(u)*v, RNE-rounded (rows >= cnt hold garbage, never read)
    #pragma unroll
    for (int mi = 0; mi < 2; mi++) {
        #pragma unroll
        for (int ni = 0; ni < 4; ni++) {
            int row = base + m0 + wm + mi*16 + g;
            int col = n0 + wn + ni*8 + tg*2;
            size_t baseo = (size_t)row*FFN + col;
            float u0 = acc1[mi][ni][0], u1 = acc1[mi][ni][1];
            float v0 = acc3[mi][ni][0], v1 = acc3[mi][ni][1];
            *(float2*)&g_h[baseo] = make_float2(
                rnef(v0 * (u0 / (1.0f + __expf(-u0)))),
                rnef(v1 * (u1 / (1.0f + __expf(-u1)))));
            float u2 = acc1[mi][ni][2], u3 = acc1[mi][ni][3];
            float v2 = acc3[mi][ni][2], v3 = acc3[mi][ni][3];
            *(float2*)&g_h[baseo + (size_t)8*FFN] = make_float2(
                rnef(v2 * (u2 / (1.0f + __expf(-u2)))),
                rnef(v3 * (u3 / (1.0f + __expf(-u3)))));
        }
    }
}

// ---------------- GEMM2: y = H@W2^T ----------------
__global__ void __launch_bounds__(288, 2)
gemm2_k(const __grid_constant__ CUtensorMap a_map,
        const __grid_constant__ CUtensorMap b_map)
{
    const int e = blockIdx.z;
    const int cnt = g_counts[e];
    const int m0 = blockIdx.x * BM;
    if (m0 >= cnt) return;
    const int base = g_base[e];
    const int n0 = blockIdx.y * BN;

    extern __shared__ __align__(1024) char smem[];
    const uint32_t sb = smem_u32(smem);
    const int tid = threadIdx.x, wid = tid >> 5, lane = tid & 31;

    if (tid == 0) {
        #pragma unroll
        for (int s = 0; s < ST2; s++) { MBAR_INIT(sb+FULL_OFF(s), 1); MBAR_INIT(sb+EMPTY_OFF(s), 8); }
    }
    __syncthreads();

    if (wid == 8) {                 // producer
        int s = 0, ph = 1;
        #pragma unroll 1
        for (int kt = 0; kt < KT2; kt++) {
            MBAR_WAIT(sb+EMPTY_OFF(s), ph);
            if (elect_one()) {
                MBAR_EXPECT_TX(sb+FULL_OFF(s), A_BYTES + B_BYTES);
                tma2d(sb+SM2_A(s), &a_map, kt*BK, base + m0,  sb+FULL_OFF(s));
                tma2d(sb+SM2_B(s), &b_map, kt*BK, e*DIM + n0, sb+FULL_OFF(s));
            }
            if (++s == ST2) { s = 0; ph ^= 1; }
        }
        return;
    }

    const int wm = (wid & 3) * 32, wn = (wid >> 2) * 32;
    const int g = lane >> 2, tg = lane & 3;
    const uint32_t mk = (uint32_t)g << 4;

    uint32_t aRow[4], bRow[4], cofs[4][2];
    #pragma unroll
    for (int i = 0; i < 4; i++) aRow[i] = (uint32_t)(wm + g + i*8) * 128;
    #pragma unroll
    for (int i = 0; i < 4; i++) bRow[i] = (uint32_t)(wn + i*8 + g) * 128;
    #pragma unroll
    for (int kk = 0; kk < 4; kk++) {
        cofs[kk][0] = ((uint32_t)(kk*8 + tg)     * 4) ^ mk;
        cofs[kk][1] = ((uint32_t)(kk*8 + tg + 4) * 4) ^ mk;
    }

    float acc[2][4][4] = {};
    int s = 0, ph = 0;
    #pragma unroll 1
    for (int kt = 0; kt < KT2; kt++) {
        MBAR_WAIT(sb+FULL_OFF(s), ph);
        const uint32_t At = sb + SM2_A(s), Bt = sb + SM2_B(s);
        #pragma unroll
        for (int kk = 0; kk < 4; kk++) {
            uint32_t a[2][4];
            #pragma unroll
            for (int mi = 0; mi < 2; mi++) {
                a[mi][0] = lds_u32(At + aRow[2*mi]   + cofs[kk][0]);
                a[mi][1] = lds_u32(At + aRow[2*mi+1] + cofs[kk][0]);
                a[mi][2] = lds_u32(At + aRow[2*mi]   + cofs[kk][1]);
                a[mi][3] = lds_u32(At + aRow[2*mi+1] + cofs[kk][1]);
            }
            #pragma unroll
            for (int ni = 0; ni < 4; ni++) {
                uint32_t b[2];
                b[0] = lds_u32(Bt + bRow[ni] + cofs[kk][0]);
                b[1] = lds_u32(Bt + bRow[ni] + cofs[kk][1]);
                #pragma unroll
                for (int mi = 0; mi < 2; mi++) mma_tf32(acc[mi][ni], a[mi], b);
            }
        }
        __syncwarp();
        if (lane == 0) MBAR_ARRIVE(sb+EMPTY_OFF(s));
        if (++s == ST2) { s = 0; ph ^= 1; }
    }

    #pragma unroll
    for (int mi = 0; mi < 2; mi++) {
        #pragma unroll
        for (int ni = 0; ni < 4; ni++) {
            int row = base + m0 + wm + mi*16 + g;
            int col = n0 + wn + ni*8 + tg*2;
            size_t baseo = (size_t)row*DIM + col;
            *(float2*)&g_y[baseo]                 = make_float2(acc[mi][ni][0], acc[mi][ni][1]);
            *(float2*)&g_y[baseo + (size_t)8*DIM] = make_float2(acc[mi][ni][2], acc[mi][ni][3]);
        }
    }
}

// ---------------- final gather ----------------
__global__ void gather_k(const int* __restrict__ map, const float* __restrict__ probs,
                         float* __restrict__ out) {
    const int t = blockIdx.x, tid = threadIdx.x;
    float4 acc0 = make_float4(0.f, 0.f, 0.f, 0.f);
    float4 acc1 = make_float4(0.f, 0.f, 0.f, 0.f);
    #pragma unroll
    for (int e = 0; e < NE; e++) {
        if (map[t*NE + e]) {
            float p = probs[t*NE + e];
            int row = g_base[e] + g_slot_of[t*NE + e];
            const float4* yr = (const float4*)(g_y + (size_t)row*DIM);
            float4 y0 = yr[tid], y1 = yr[tid + 256];
            acc0.x += p*y0.x; acc0.y += p*y0.y; acc0.z += p*y0.z; acc0.w += p*y0.w;
            acc1.x += p*y1.x; acc1.y += p*y1.y; acc1.z += p*y1.z; acc1.w += p*y1.w;
        }
    }
    float4* o = (float4*)(out + (size_t)t*DIM);
    o[tid]       = acc0;
    o[tid + 256] = acc1;
}

// ---------------- host ----------------
typedef CUresult (*EncodeFn)(CUtensorMap*, CUtensorMapDataType, cuuint32_t, void*,
                             const cuuint64_t*, const cuuint64_t*, const cuuint32_t*,
                             const cuuint32_t*, CUtensorMapInterleave, CUtensorMapSwizzle,
                             CUtensorMapL2promotion, CUtensorMapFloatOOBfill);

static void make_map(EncodeFn enc, CUtensorMap* m, void* base,
                     uint64_t d0, uint64_t d1, uint32_t b0, uint32_t b1) {
    cuuint64_t dims[2] = {d0, d1};
    cuuint64_t strides[1] = {d0 * 4};
    cuuint32_t box[2] = {b0, b1};
    cuuint32_t es[2] = {1, 1};
    enc(m, CU_TENSOR_MAP_DATA_TYPE_FLOAT32, 2, base, dims, strides, box, es,
        CU_TENSOR_MAP_INTERLEAVE_NONE, CU_TENSOR_MAP_SWIZZLE_128B,
        CU_TENSOR_MAP_L2_PROMOTION_L2_128B, CU_TENSOR_MAP_FLOAT_OOB_FILL_NONE);
}

extern "C" void kernel_launch(void* const* d_in, const int* in_sizes, int n_in,
                              void* d_out, int out_size) {
    const float* x     = (const float*)d_in[0];
    const int*   map   = (const int*)  d_in[1];
    const float* probs = (const float*)d_in[2];
    const float* w1    = (const float*)d_in[3];
    const float* w2    = (const float*)d_in[4];
    const float* w3    = (const float*)d_in[5];
    float*       out   = (float*)d_out;

    void *p_xp, *p_w1, *p_w2, *p_w3, *p_h;
    cudaGetSymbolAddress(&p_xp, g_xp);
    cudaGetSymbolAddress(&p_w1, g_w1);
    cudaGetSymbolAddress(&p_w2, g_w2);
    cudaGetSymbolAddress(&p_w3, g_w3);
    cudaGetSymbolAddress(&p_h,  g_h);

    EncodeFn enc = nullptr;
    cudaDriverEntryPointQueryResult qr;
    cudaGetDriverEntryPointByVersion("cuTensorMapEncodeTiled", (void**)&enc, 12000,
                                     cudaEnableDefault, &qr);

    CUtensorMap mA1, mB1, mB3, mA2, mB2;
    make_map(enc, &mA1, p_xp, DIM, NROWS,            BK, BM);
    make_map(enc, &mB1, p_w1, DIM, (uint64_t)NE*FFN, BK, BN);
    make_map(enc, &mB3, p_w3, DIM, (uint64_t)NE*FFN, BK, BN);
    make_map(enc, &mA2, p_h,  FFN, NROWS,            BK, BM);
    make_map(enc, &mB2, p_w2, FFN, (uint64_t)NE*DIM, BK, BN);

    cudaFuncSetAttribute(gemm1_k, cudaFuncAttributeMaxDynamicSharedMemorySize, SM1_TOTAL);
    cudaFuncSetAttribute(gemm2_k, cudaFuncAttributeMaxDynamicSharedMemorySize, SM2_TOTAL);

    const int n4w = (int)((size_t)NE*FFN*DIM/4);

    zero_counts_k<<<1, 32>>>();
    route_k<<<(NT + 255)/256, 256>>>(map);
    base_k<<<1, 32>>>();
    permute_round_k<<<NT, 256>>>(x, map);
    round_k<<<(n4w + 255)/256, 256>>>((const float4*)w1, (float4*)p_w1, n4w);
    round_k<<<(n4w + 255)/256, 256>>>((const float4*)w3, (float4*)p_w3, n4w);
    round_k<<<(n4w + 255)/256, 256>>>((const float4*)w2, (float4*)p_w2, n4w);
    gemm1_k<<<dim3(NT/BM, FFN/BN, NE), 288, SM1_TOTAL>>>(mA1, mB1, mB3);
    gemm2_k<<<dim3(NT/BM, DIM/BN, NE), 288, SM2_TOTAL>>>(mA2, mB2);
    gather_k<<<NT, 256>>>(map, probs, out);
}